// round 2
// baseline (speedup 1.0000x reference)
#include <cuda_runtime.h>

// Problem dims
#define T_DIM 4
#define B_DIM 32
#define C_DIM 512
#define N_DIM 196
#define H_DIM 2048
#define J_DIM (B_DIM * N_DIM)          // 6272 = 49 * 128
#define HJ (H_DIM * J_DIM)             // 12,845,056
#define CJ (C_DIM * J_DIM)             //  3,211,264

// Scratch (static device memory; no allocations allowed)
__device__ float g_xT[T_DIM * CJ];     // x transposed: (t, c, j)   51.4 MB
__device__ float g_h[T_DIM * HJ];      // hidden pre-act / spikes  205.5 MB (in-place)
__device__ float g_o[T_DIM * CJ];      // output pre-act            51.4 MB
__device__ float g_mean1[H_DIM];
__device__ float g_rstd1[H_DIM];
__device__ float g_mean2[C_DIM];
__device__ float g_rstd2[C_DIM];

// ---------------------------------------------------------------------------
// K0: transpose x (t,b,c,n) -> g_xT (t,c,b*n). Write-coalesced; reads are
// contiguous 196-float runs.
// ---------------------------------------------------------------------------
__global__ void transpose_x(const float* __restrict__ x) {
    int idx = blockIdx.x * blockDim.x + threadIdx.x;
    if (idx >= T_DIM * CJ) return;
    int t   = idx / CJ;
    int rem = idx - t * CJ;
    int c   = rem / J_DIM;
    int j   = rem - c * J_DIM;
    int b   = j / N_DIM;
    int n   = j - b * N_DIM;
    g_xT[idx] = x[((t * B_DIM + b) * C_DIM + c) * N_DIM + n];
}

// ---------------------------------------------------------------------------
// SGEMM: C[m,j] = sum_k A[m,k] * B[k,j], per-batch (blockIdx.z).
// A row-major [M,K]; B,C have row stride J_DIM. 128x128 tile, BK=8,
// 256 threads, 8x8 accumulators. All dims divide exactly (no bounds checks).
// ---------------------------------------------------------------------------
__global__ __launch_bounds__(256) void sgemm_batched(
    const float* __restrict__ A, const float* __restrict__ B,
    float* __restrict__ C, int M, int K, int bStrideB, int bStrideC) {
    __shared__ float As[8][128];
    __shared__ float Bs[8][128];

    const float* Bt = B + blockIdx.z * bStrideB;
    float*       Ct = C + blockIdx.z * bStrideC;

    int tid  = threadIdx.x;
    int m0   = blockIdx.x * 128;
    int n0   = blockIdx.y * 128;

    int arow = tid >> 1;            // 0..127
    int acol = (tid & 1) << 2;      // 0 or 4
    int brow = tid >> 5;            // 0..7
    int bcol = (tid & 31) << 2;     // 0..124

    const float* Ap = A  + (m0 + arow) * K + acol;
    const float* Bp = Bt + brow * J_DIM + n0 + bcol;

    int ty = (tid >> 4) << 3;       // 0..120 step 8
    int tx = (tid & 15) << 3;

    float acc[8][8];
#pragma unroll
    for (int i = 0; i < 8; i++)
#pragma unroll
        for (int j = 0; j < 8; j++) acc[i][j] = 0.0f;

    for (int k0 = 0; k0 < K; k0 += 8) {
        float4 a4 = *(const float4*)Ap;
        float4 b4 = *(const float4*)Bp;
        As[acol + 0][arow] = a4.x;
        As[acol + 1][arow] = a4.y;
        As[acol + 2][arow] = a4.z;
        As[acol + 3][arow] = a4.w;
        *(float4*)&Bs[brow][bcol] = b4;
        __syncthreads();

#pragma unroll
        for (int k = 0; k < 8; k++) {
            float4 ra0 = *(const float4*)&As[k][ty];
            float4 ra1 = *(const float4*)&As[k][ty + 4];
            float4 rb0 = *(const float4*)&Bs[k][tx];
            float4 rb1 = *(const float4*)&Bs[k][tx + 4];
            float ra[8] = {ra0.x, ra0.y, ra0.z, ra0.w, ra1.x, ra1.y, ra1.z, ra1.w};
            float rb[8] = {rb0.x, rb0.y, rb0.z, rb0.w, rb1.x, rb1.y, rb1.z, rb1.w};
#pragma unroll
            for (int i = 0; i < 8; i++)
#pragma unroll
                for (int j = 0; j < 8; j++)
                    acc[i][j] = fmaf(ra[i], rb[j], acc[i][j]);
        }
        __syncthreads();
        Ap += 8;
        Bp += 8 * J_DIM;
    }

#pragma unroll
    for (int i = 0; i < 8; i++) {
        float* cr = Ct + (m0 + ty + i) * J_DIM + n0 + tx;
        *(float4*)cr       = make_float4(acc[i][0], acc[i][1], acc[i][2], acc[i][3]);
        *(float4*)(cr + 4) = make_float4(acc[i][4], acc[i][5], acc[i][6], acc[i][7]);
    }
}

// ---------------------------------------------------------------------------
// BN stats: one CTA per channel; fp64 accumulation so mean/var match the
// reference to ~1e-9 (spike-threshold sensitivity demands this).
// X layout: (t, ch, j) with time stride tStride.
// ---------------------------------------------------------------------------
__global__ __launch_bounds__(256) void bn_stats(
    const float* __restrict__ X, int tStride,
    float* __restrict__ meanOut, float* __restrict__ rstdOut) {
    int ch = blockIdx.x;
    const float* base = X + ch * J_DIM;
    double s1 = 0.0, s2 = 0.0;
    for (int t = 0; t < T_DIM; t++) {
        const float* p = base + t * tStride;
        for (int j = threadIdx.x; j < J_DIM; j += 256) {
            double v = (double)p[j];
            s1 += v;
            s2 += v * v;
        }
    }
    __shared__ double sh1[256];
    __shared__ double sh2[256];
    sh1[threadIdx.x] = s1;
    sh2[threadIdx.x] = s2;
    __syncthreads();
    for (int s = 128; s > 0; s >>= 1) {
        if (threadIdx.x < s) {
            sh1[threadIdx.x] += sh1[threadIdx.x + s];
            sh2[threadIdx.x] += sh2[threadIdx.x + s];
        }
        __syncthreads();
    }
    if (threadIdx.x == 0) {
        double n    = (double)T_DIM * (double)J_DIM;
        double mean = sh1[0] / n;
        double var  = sh2[0] / n - mean * mean;
        float  vf   = (float)var;
        meanOut[ch] = (float)mean;
        rstdOut[ch] = __frsqrt_rn(__fadd_rn(vf, 1e-5f));
    }
}

// ---------------------------------------------------------------------------
// BN-apply + LIF, layer 1, IN PLACE on g_h (pre-act -> spikes).
// Rounding sequence pinned with __f*_rn to match the reference's
// (x-mean)*rstd*gamma+beta then v += (x - v)*0.5 semantics (no FMA fusion).
// ---------------------------------------------------------------------------
__global__ __launch_bounds__(256) void bn_lif1(
    const float* __restrict__ gamma, const float* __restrict__ beta) {
    int idx = blockIdx.x * blockDim.x + threadIdx.x;
    if (idx >= HJ) return;
    int ch = idx / J_DIM;
    float m = g_mean1[ch], r = g_rstd1[ch];
    float g = gamma[ch],   bt = beta[ch];
    float v = 0.0f;
#pragma unroll
    for (int t = 0; t < T_DIM; t++) {
        float x = g_h[idx + t * HJ];
        x = __fadd_rn(__fmul_rn(__fmul_rn(__fsub_rn(x, m), r), g), bt);
        v = __fadd_rn(v, __fmul_rn(__fsub_rn(x, v), 0.5f));
        float s = (v >= 1.0f) ? 1.0f : 0.0f;
        g_h[idx + t * HJ] = s;
        v = (v >= 1.0f) ? 0.0f : v;
    }
}

// ---------------------------------------------------------------------------
// BN-apply + LIF, layer 2, reading g_o (t,c,j) and writing d_out (t,b,c,n).
// ---------------------------------------------------------------------------
__global__ __launch_bounds__(256) void bn_lif2(
    const float* __restrict__ gamma, const float* __restrict__ beta,
    float* __restrict__ out) {
    int idx = blockIdx.x * blockDim.x + threadIdx.x;
    if (idx >= CJ) return;
    int c = idx / J_DIM;
    int j = idx - c * J_DIM;
    int b = j / N_DIM;
    int n = j - b * N_DIM;
    float m = g_mean2[c], r = g_rstd2[c];
    float g = gamma[c],   bt = beta[c];
    float v = 0.0f;
#pragma unroll
    for (int t = 0; t < T_DIM; t++) {
        float x = g_o[idx + t * CJ];
        x = __fadd_rn(__fmul_rn(__fmul_rn(__fsub_rn(x, m), r), g), bt);
        v = __fadd_rn(v, __fmul_rn(__fsub_rn(x, v), 0.5f));
        float s = (v >= 1.0f) ? 1.0f : 0.0f;
        out[((t * B_DIM + b) * C_DIM + c) * N_DIM + n] = s;
        v = (v >= 1.0f) ? 0.0f : v;
    }
}

// ---------------------------------------------------------------------------
// kernel_launch: 7 kernels, default stream, graph-capturable.
// Inputs: 0:x 1:w1 2:g1 3:b1 4:w2 5:g2 6:b2
// ---------------------------------------------------------------------------
extern "C" void kernel_launch(void* const* d_in, const int* in_sizes, int n_in,
                              void* d_out, int out_size) {
    const float* x  = (const float*)d_in[0];
    const float* w1 = (const float*)d_in[1];
    const float* g1 = (const float*)d_in[2];
    const float* b1 = (const float*)d_in[3];
    const float* w2 = (const float*)d_in[4];
    const float* g2 = (const float*)d_in[5];
    const float* b2 = (const float*)d_in[6];
    float* out = (float*)d_out;

    float *p_xT, *p_h, *p_o, *p_m1, *p_r1, *p_m2, *p_r2;
    cudaGetSymbolAddress((void**)&p_xT, g_xT);
    cudaGetSymbolAddress((void**)&p_h,  g_h);
    cudaGetSymbolAddress((void**)&p_o,  g_o);
    cudaGetSymbolAddress((void**)&p_m1, g_mean1);
    cudaGetSymbolAddress((void**)&p_r1, g_rstd1);
    cudaGetSymbolAddress((void**)&p_m2, g_mean2);
    cudaGetSymbolAddress((void**)&p_r2, g_rstd2);

    // K0: transpose x
    transpose_x<<<(T_DIM * CJ) / 256, 256>>>(x);

    // K1: h = w1 @ xT   per t:  [2048,512] x [512,6272]
    sgemm_batched<<<dim3(H_DIM / 128, J_DIM / 128, T_DIM), 256>>>(
        w1, p_xT, p_h, H_DIM, C_DIM, CJ, HJ);

    // K2: BN1 stats
    bn_stats<<<H_DIM, 256>>>(p_h, HJ, p_m1, p_r1);

    // K3: BN1 + LIF1 (in place: g_h becomes spikes)
    bn_lif1<<<HJ / 256, 256>>>(g1, b1);

    // K4: o = w2 @ spikes   per t:  [512,2048] x [2048,6272]
    sgemm_batched<<<dim3(C_DIM / 128, J_DIM / 128, T_DIM), 256>>>(
        w2, p_h, p_o, C_DIM, H_DIM, HJ, CJ);

    // K5: BN2 stats
    bn_stats<<<C_DIM, 256>>>(p_o, CJ, p_m2, p_r2);

    // K6: BN2 + LIF2 + transpose to (T,B,C,N)
    bn_lif2<<<CJ / 256, 256>>>(g2, b2, out);
}

// round 3
// speedup vs baseline: 2.1050x; 2.1050x over previous
#include <cuda_runtime.h>

// Problem dims
#define T_DIM 4
#define B_DIM 32
#define C_DIM 512
#define N_DIM 196
#define H_DIM 2048
#define J_DIM (B_DIM * N_DIM)          // 6272 = 49 * 128
#define HJ (H_DIM * J_DIM)             // 12,845,056
#define CJ (C_DIM * J_DIM)             //  3,211,264

// Scratch (static device memory)
__device__ float g_xT[T_DIM * CJ];     // x transposed: (t, c, j)
__device__ float g_h[T_DIM * HJ];      // hidden pre-act / spikes (in place)
__device__ float g_o[T_DIM * CJ];      // output pre-act
__device__ float g_w2T[H_DIM * C_DIM]; // w2 transposed to [H, C]
__device__ float g_mean1[H_DIM];
__device__ float g_rstd1[H_DIM];
__device__ float g_mean2[C_DIM];
__device__ float g_rstd2[C_DIM];

// ---------------------------------------------------------------------------
// K0: transpose x (t,b,c,n) -> g_xT (t,c,j=b*n), float4 both sides.
// ---------------------------------------------------------------------------
__global__ void transpose_x(const float* __restrict__ x) {
    int idx = blockIdx.x * blockDim.x + threadIdx.x;   // over T*CJ/4
    int base = idx << 2;
    int t   = base / CJ;
    int rem = base - t * CJ;
    int c   = rem / J_DIM;
    int j   = rem - c * J_DIM;
    int b   = j / N_DIM;
    int n   = j - b * N_DIM;                            // n%4==0, n+3<196
    float4 v = *(const float4*)&x[((t * B_DIM + b) * C_DIM + c) * N_DIM + n];
    *(float4*)&g_xT[base] = v;
}

// ---------------------------------------------------------------------------
// K0b: transpose w2 [C,H] -> g_w2T [H,C]
// ---------------------------------------------------------------------------
__global__ void transpose_w2(const float* __restrict__ w2) {
    __shared__ float tile[32][33];
    int h0 = blockIdx.x * 32, c0 = blockIdx.y * 32;
    for (int r = threadIdx.y; r < 32; r += 8)
        tile[r][threadIdx.x] = w2[(c0 + r) * H_DIM + h0 + threadIdx.x];
    __syncthreads();
    for (int r = threadIdx.y; r < 32; r += 8)
        g_w2T[(h0 + r) * C_DIM + c0 + threadIdx.x] = tile[threadIdx.x][r];
}

// ---------------------------------------------------------------------------
// K1: SGEMM h = w1 @ xT per t. M=2048, K=512, N-tile over J.
// 128x128 tile, BK=8, 256 threads, 8x8/thread with 4+64 split layout
// (conflict-free LDS.128), double-buffered smem, one sync per k-tile.
// ---------------------------------------------------------------------------
__global__ __launch_bounds__(256) void sgemm1(
    const float* __restrict__ A, const float* __restrict__ B,
    float* __restrict__ C) {
    __shared__ float As[2][8][128];
    __shared__ float Bs[2][8][128];

    const float* Bt = B + blockIdx.z * CJ;
    float*       Ct = C + blockIdx.z * HJ;

    int tid = threadIdx.x;
    int m0 = blockIdx.x * 128;
    int n0 = blockIdx.y * 128;

    int arow = tid >> 1;            // 0..127
    int acol = (tid & 1) << 2;      // 0 or 4
    int brow = tid >> 5;            // 0..7
    int bcol = (tid & 31) << 2;     // 0..124

    const float* Ap = A  + (m0 + arow) * 512 + acol;
    const float* Bp = Bt + brow * J_DIM + n0 + bcol;

    int tx = tid & 15;              // column group
    int ty = tid >> 4;              // row group

    float acc[8][8];
#pragma unroll
    for (int i = 0; i < 8; i++)
#pragma unroll
        for (int j = 0; j < 8; j++) acc[i][j] = 0.0f;

    // prologue: first tile
    float4 a4 = *(const float4*)Ap;
    float4 b4 = *(const float4*)Bp;
    As[0][acol + 0][arow] = a4.x;
    As[0][acol + 1][arow] = a4.y;
    As[0][acol + 2][arow] = a4.z;
    As[0][acol + 3][arow] = a4.w;
    *(float4*)&Bs[0][brow][bcol] = b4;
    __syncthreads();

    int buf = 0;
    for (int k0 = 8; k0 <= 512; k0 += 8) {
        bool more = (k0 < 512);
        if (more) {
            Ap += 8;
            Bp += 8 * J_DIM;
            a4 = *(const float4*)Ap;
            b4 = *(const float4*)Bp;
        }
#pragma unroll
        for (int k = 0; k < 8; k++) {
            float4 ra0 = *(const float4*)&As[buf][k][ty << 2];
            float4 ra1 = *(const float4*)&As[buf][k][(ty << 2) + 64];
            float4 rb0 = *(const float4*)&Bs[buf][k][tx << 2];
            float4 rb1 = *(const float4*)&Bs[buf][k][(tx << 2) + 64];
            float ra[8] = {ra0.x, ra0.y, ra0.z, ra0.w, ra1.x, ra1.y, ra1.z, ra1.w};
            float rb[8] = {rb0.x, rb0.y, rb0.z, rb0.w, rb1.x, rb1.y, rb1.z, rb1.w};
#pragma unroll
            for (int i = 0; i < 8; i++)
#pragma unroll
                for (int j = 0; j < 8; j++)
                    acc[i][j] = fmaf(ra[i], rb[j], acc[i][j]);
        }
        if (more) {
            buf ^= 1;
            As[buf][acol + 0][arow] = a4.x;
            As[buf][acol + 1][arow] = a4.y;
            As[buf][acol + 2][arow] = a4.z;
            As[buf][acol + 3][arow] = a4.w;
            *(float4*)&Bs[buf][brow][bcol] = b4;
            __syncthreads();
        }
    }

#pragma unroll
    for (int i = 0; i < 8; i++) {
        int m = m0 + (ty << 2) + ((i < 4) ? i : (60 + i));   // 4+64 split rows
        float* cr = Ct + m * J_DIM + n0 + (tx << 2);
        *(float4*)cr        = make_float4(acc[i][0], acc[i][1], acc[i][2], acc[i][3]);
        *(float4*)(cr + 64) = make_float4(acc[i][4], acc[i][5], acc[i][6], acc[i][7]);
    }
}

// ---------------------------------------------------------------------------
// BN stats: one CTA per channel, fp64 accumulate, float4 loads.
// ---------------------------------------------------------------------------
__global__ __launch_bounds__(256) void bn_stats(
    const float* __restrict__ X, int tStride,
    float* __restrict__ meanOut, float* __restrict__ rstdOut) {
    int ch = blockIdx.x;
    const float* base = X + ch * J_DIM;
    double s1 = 0.0, s2 = 0.0;
    for (int t = 0; t < T_DIM; t++) {
        const float* p = base + t * tStride;
        for (int j = threadIdx.x * 4; j < J_DIM; j += 256 * 4) {
            float4 v = *(const float4*)&p[j];
            double a = v.x, b = v.y, c = v.z, d = v.w;
            s1 += a + b + c + d;
            s2 += a * a + b * b + c * c + d * d;
        }
    }
    __shared__ double sh1[256];
    __shared__ double sh2[256];
    sh1[threadIdx.x] = s1;
    sh2[threadIdx.x] = s2;
    __syncthreads();
    for (int s = 128; s > 0; s >>= 1) {
        if (threadIdx.x < s) {
            sh1[threadIdx.x] += sh1[threadIdx.x + s];
            sh2[threadIdx.x] += sh2[threadIdx.x + s];
        }
        __syncthreads();
    }
    if (threadIdx.x == 0) {
        double n    = (double)T_DIM * (double)J_DIM;
        double mean = sh1[0] / n;
        double var  = sh2[0] / n - mean * mean;
        float  vf   = (float)var;
        meanOut[ch] = (float)mean;
        rstdOut[ch] = __frsqrt_rn(__fadd_rn(vf, 1e-5f));
    }
}

// ---------------------------------------------------------------------------
// BN1 + LIF1 in place on g_h (pre-act -> spikes), float4.
// Rounding pinned with __f*_rn (no FMA contraction).
// ---------------------------------------------------------------------------
__global__ __launch_bounds__(256) void bn_lif1(
    const float* __restrict__ gamma, const float* __restrict__ beta) {
    int idx = blockIdx.x * blockDim.x + threadIdx.x;   // over HJ/4
    int base = idx << 2;
    int ch = base / J_DIM;
    float m = g_mean1[ch], r = g_rstd1[ch];
    float g = gamma[ch],   bt = beta[ch];
    float v0 = 0.f, v1 = 0.f, v2 = 0.f, v3 = 0.f;
#pragma unroll
    for (int t = 0; t < T_DIM; t++) {
        float4 x = *(const float4*)&g_h[base + t * HJ];
        float a0 = __fadd_rn(__fmul_rn(__fmul_rn(__fsub_rn(x.x, m), r), g), bt);
        float a1 = __fadd_rn(__fmul_rn(__fmul_rn(__fsub_rn(x.y, m), r), g), bt);
        float a2 = __fadd_rn(__fmul_rn(__fmul_rn(__fsub_rn(x.z, m), r), g), bt);
        float a3 = __fadd_rn(__fmul_rn(__fmul_rn(__fsub_rn(x.w, m), r), g), bt);
        v0 = __fadd_rn(v0, __fmul_rn(__fsub_rn(a0, v0), 0.5f));
        v1 = __fadd_rn(v1, __fmul_rn(__fsub_rn(a1, v1), 0.5f));
        v2 = __fadd_rn(v2, __fmul_rn(__fsub_rn(a2, v2), 0.5f));
        v3 = __fadd_rn(v3, __fmul_rn(__fsub_rn(a3, v3), 0.5f));
        float4 s;
        s.x = (v0 >= 1.0f) ? 1.0f : 0.0f;
        s.y = (v1 >= 1.0f) ? 1.0f : 0.0f;
        s.z = (v2 >= 1.0f) ? 1.0f : 0.0f;
        s.w = (v3 >= 1.0f) ? 1.0f : 0.0f;
        *(float4*)&g_h[base + t * HJ] = s;
        v0 = (v0 >= 1.0f) ? 0.0f : v0;
        v1 = (v1 >= 1.0f) ? 0.0f : v1;
        v2 = (v2 >= 1.0f) ? 0.0f : v2;
        v3 = (v3 >= 1.0f) ? 0.0f : v3;
    }
}

// ---------------------------------------------------------------------------
// K4: sparse spike GEMM.  o[:, j] = sum over active h of w2T[h, :].
// One CTA = 32 j-columns x one t. 32 warps; warp w owns column j0+w.
// Phase 1: ballot spike bits into per-h words (bit l = column j0+l).
// Phase 2: per 32-h chunk, re-ballot to a per-column h-mask, ffs-iterate
//          only active rows; lane accumulates c = lane*4 + q*128 + {0..3}.
// Epilogue: stage through smem for coalesced g_o writes.
// ---------------------------------------------------------------------------
__global__ __launch_bounds__(1024) void spmm2() {
    __shared__ unsigned words[H_DIM];        // 8 KB
    __shared__ float buf[128 * 33];          // 16.9 KB

    int tid  = threadIdx.x;
    int w    = tid >> 5;                     // warp id = local column
    int lane = tid & 31;
    int j0   = blockIdx.x * 32;
    int t    = blockIdx.y;

    // Phase 1: spike bitmask. Warp reads 32 consecutive j for one h (coalesced).
    const float* sp = g_h + t * HJ + j0 + lane;
    for (int h = w; h < H_DIM; h += 32) {
        float sv = sp[h * J_DIM];
        unsigned m = __ballot_sync(0xffffffffu, sv != 0.0f);
        if (lane == 0) words[h] = m;
    }
    __syncthreads();

    // Phase 2: accumulate active rows of w2T for column j0+w.
    float4 acc0 = make_float4(0.f, 0.f, 0.f, 0.f);
    float4 acc1 = acc0, acc2 = acc0, acc3 = acc0;
    int c0 = lane << 2;
    for (int wi = 0; wi < H_DIM / 32; wi++) {
        unsigned bit = (words[(wi << 5) + lane] >> w) & 1u;
        unsigned m = __ballot_sync(0xffffffffu, bit);
        while (m) {
            int b = __ffs(m) - 1;
            m &= m - 1;
            int h = (wi << 5) + b;
            const float* rp = g_w2T + h * C_DIM + c0;
            float4 v0 = *(const float4*)(rp);
            float4 v1 = *(const float4*)(rp + 128);
            float4 v2 = *(const float4*)(rp + 256);
            float4 v3 = *(const float4*)(rp + 384);
            acc0.x += v0.x; acc0.y += v0.y; acc0.z += v0.z; acc0.w += v0.w;
            acc1.x += v1.x; acc1.y += v1.y; acc1.z += v1.z; acc1.w += v1.w;
            acc2.x += v2.x; acc2.y += v2.y; acc2.z += v2.z; acc2.w += v2.w;
            acc3.x += v3.x; acc3.y += v3.y; acc3.z += v3.z; acc3.w += v3.w;
        }
    }

    // Epilogue: 4 chunks of 128 c-rows, staged for coalesced writes.
#pragma unroll
    for (int q = 0; q < 4; q++) {
        float4 a = (q == 0) ? acc0 : (q == 1) ? acc1 : (q == 2) ? acc2 : acc3;
        __syncthreads();
        buf[(c0 + 0) * 33 + w] = a.x;
        buf[(c0 + 1) * 33 + w] = a.y;
        buf[(c0 + 2) * 33 + w] = a.z;
        buf[(c0 + 3) * 33 + w] = a.w;
        __syncthreads();
        int c_local = tid >> 3;              // 0..127
        int jj = (tid & 7) << 2;             // 0..28
        float4 o;
        o.x = buf[c_local * 33 + jj + 0];
        o.y = buf[c_local * 33 + jj + 1];
        o.z = buf[c_local * 33 + jj + 2];
        o.w = buf[c_local * 33 + jj + 3];
        *(float4*)&g_o[t * CJ + (q * 128 + c_local) * J_DIM + j0 + jj] = o;
    }
}

// ---------------------------------------------------------------------------
// BN2 + LIF2 + transpose to (T,B,C,N), float4.
// ---------------------------------------------------------------------------
__global__ __launch_bounds__(256) void bn_lif2(
    const float* __restrict__ gamma, const float* __restrict__ beta,
    float* __restrict__ out) {
    int idx = blockIdx.x * blockDim.x + threadIdx.x;   // over CJ/4
    int base = idx << 2;
    int c = base / J_DIM;
    int j = base - c * J_DIM;
    int b = j / N_DIM;
    int n = j - b * N_DIM;                              // n%4==0, n+3<196
    float m = g_mean2[c], r = g_rstd2[c];
    float g = gamma[c],   bt = beta[c];
    float v0 = 0.f, v1 = 0.f, v2 = 0.f, v3 = 0.f;
#pragma unroll
    for (int t = 0; t < T_DIM; t++) {
        float4 x = *(const float4*)&g_o[base + t * CJ];
        float a0 = __fadd_rn(__fmul_rn(__fmul_rn(__fsub_rn(x.x, m), r), g), bt);
        float a1 = __fadd_rn(__fmul_rn(__fmul_rn(__fsub_rn(x.y, m), r), g), bt);
        float a2 = __fadd_rn(__fmul_rn(__fmul_rn(__fsub_rn(x.z, m), r), g), bt);
        float a3 = __fadd_rn(__fmul_rn(__fmul_rn(__fsub_rn(x.w, m), r), g), bt);
        v0 = __fadd_rn(v0, __fmul_rn(__fsub_rn(a0, v0), 0.5f));
        v1 = __fadd_rn(v1, __fmul_rn(__fsub_rn(a1, v1), 0.5f));
        v2 = __fadd_rn(v2, __fmul_rn(__fsub_rn(a2, v2), 0.5f));
        v3 = __fadd_rn(v3, __fmul_rn(__fsub_rn(a3, v3), 0.5f));
        float4 s;
        s.x = (v0 >= 1.0f) ? 1.0f : 0.0f;
        s.y = (v1 >= 1.0f) ? 1.0f : 0.0f;
        s.z = (v2 >= 1.0f) ? 1.0f : 0.0f;
        s.w = (v3 >= 1.0f) ? 1.0f : 0.0f;
        *(float4*)&out[((t * B_DIM + b) * C_DIM + c) * N_DIM + n] = s;
        v0 = (v0 >= 1.0f) ? 0.0f : v0;
        v1 = (v1 >= 1.0f) ? 0.0f : v1;
        v2 = (v2 >= 1.0f) ? 0.0f : v2;
        v3 = (v3 >= 1.0f) ? 0.0f : v3;
    }
}

// ---------------------------------------------------------------------------
// kernel_launch. Inputs: 0:x 1:w1 2:g1 3:b1 4:w2 5:g2 6:b2
// ---------------------------------------------------------------------------
extern "C" void kernel_launch(void* const* d_in, const int* in_sizes, int n_in,
                              void* d_out, int out_size) {
    const float* x  = (const float*)d_in[0];
    const float* w1 = (const float*)d_in[1];
    const float* g1 = (const float*)d_in[2];
    const float* b1 = (const float*)d_in[3];
    const float* w2 = (const float*)d_in[4];
    const float* g2 = (const float*)d_in[5];
    const float* b2 = (const float*)d_in[6];
    float* out = (float*)d_out;

    float *p_xT, *p_h, *p_o, *p_m1, *p_r1, *p_m2, *p_r2;
    cudaGetSymbolAddress((void**)&p_xT, g_xT);
    cudaGetSymbolAddress((void**)&p_h,  g_h);
    cudaGetSymbolAddress((void**)&p_o,  g_o);
    cudaGetSymbolAddress((void**)&p_m1, g_mean1);
    cudaGetSymbolAddress((void**)&p_r1, g_rstd1);
    cudaGetSymbolAddress((void**)&p_m2, g_mean2);
    cudaGetSymbolAddress((void**)&p_r2, g_rstd2);

    transpose_x<<<(T_DIM * CJ / 4) / 256, 256>>>(x);
    transpose_w2<<<dim3(H_DIM / 32, C_DIM / 32), dim3(32, 8)>>>(w2);

    sgemm1<<<dim3(H_DIM / 128, J_DIM / 128, T_DIM), 256>>>(w1, p_xT, p_h);

    bn_stats<<<H_DIM, 256>>>(p_h, HJ, p_m1, p_r1);
    bn_lif1<<<(HJ / 4) / 256, 256>>>(g1, b1);

    spmm2<<<dim3(J_DIM / 32, T_DIM), 1024>>>();

    bn_stats<<<C_DIM, 256>>>(p_o, CJ, p_m2, p_r2);
    bn_lif2<<<(CJ / 4) / 256, 256>>>(g2, b2, out);
}